// round 2
// baseline (speedup 1.0000x reference)
#include <cuda_runtime.h>
#include <math.h>

#define NB     8
#define CCH    256
#define HW     16384
#define NHEADS 8
#define HCH    32
#define EPS    1e-5f

// ---------------- scratch (static device allocations; no cudaMalloc) --------
// Buffer reuse: BUF1 holds K (softmaxed) until ctx_kernel, then is reused for Q.
// BUF2 holds V until ctx_kernel.
__device__ float g_B1[NB * CCH * HW];   // 128 MB : K, then Q
__device__ float g_B2[NB * CCH * HW];   // 128 MB : V
__device__ float g_ctx[NB * NHEADS * HCH * HCH];
__device__ float g_M[NB * CCH * CCH];
__device__ float g_mx[NB * CCH];
__device__ float g_rsx[NB * CCH];
__device__ float g_asum[NB * CCH];
__device__ float g_asq[NB * CCH];
__device__ float g_ma[NB * CCH];
__device__ float g_sa[NB * CCH];

// ---------------------------------------------------------------------------
// K=256 GEMM:  C[b] = A[b] (256x256) @ B[b] (256xHW) + bias
// Block tile: 256(M) x 64(N) x 16(K); 256 threads, 8x8 microtile.
// Double-buffered smem: one __syncthreads per k-tile.
// STATS=true: do not write C; accumulate per-row sum / sumsq into asum/asq
// (the attn GEMM's output is only consumed as AdaIN statistics).
// ---------------------------------------------------------------------------
template <bool STATS>
__global__ __launch_bounds__(256, 2)
void gemm_k256(const float* __restrict__ A, long aStride,
               const float* __restrict__ B,
               const float* __restrict__ bias,
               float* __restrict__ Cout,
               float* __restrict__ asum, float* __restrict__ asq)
{
    __shared__ float As[2][16][256];
    __shared__ float Bs[2][16][64];

    const int tid   = threadIdx.x;
    const int batch = blockIdx.z;
    const int n0    = blockIdx.x * 64;
    const int tx    = tid & 7;     // N direction (8)
    const int ty    = tid >> 3;    // M direction (32)

    const float* Ab = A + (long)batch * aStride;
    const float* Bb = B + (long)batch * CCH * HW;

    float4 aReg[4];
    float4 bReg;

    // load k-tile 0 into regs
    {
        const float4* Arow = reinterpret_cast<const float4*>(Ab + tid * CCH);
        aReg[0] = Arow[0]; aReg[1] = Arow[1]; aReg[2] = Arow[2]; aReg[3] = Arow[3];
        bReg = *reinterpret_cast<const float4*>(Bb + (long)(tid >> 4) * HW + n0 + (tid & 15) * 4);
    }
    // store k-tile 0 -> buffer 0 (A transposed)
    #pragma unroll
    for (int c = 0; c < 4; c++) {
        As[0][c * 4 + 0][tid] = aReg[c].x;
        As[0][c * 4 + 1][tid] = aReg[c].y;
        As[0][c * 4 + 2][tid] = aReg[c].z;
        As[0][c * 4 + 3][tid] = aReg[c].w;
    }
    *reinterpret_cast<float4*>(&Bs[0][tid >> 4][(tid & 15) * 4]) = bReg;
    __syncthreads();

    float acc[8][8];
    #pragma unroll
    for (int i = 0; i < 8; i++)
        #pragma unroll
        for (int j = 0; j < 8; j++) acc[i][j] = 0.f;

    #pragma unroll 1
    for (int kt = 0; kt < 16; kt++) {
        const int cur = kt & 1;

        if (kt < 15) {  // prefetch next tile (global -> regs), hidden by compute
            const float4* Arow = reinterpret_cast<const float4*>(Ab + tid * CCH + (kt + 1) * 16);
            aReg[0] = Arow[0]; aReg[1] = Arow[1]; aReg[2] = Arow[2]; aReg[3] = Arow[3];
            bReg = *reinterpret_cast<const float4*>(
                Bb + (long)((kt + 1) * 16 + (tid >> 4)) * HW + n0 + (tid & 15) * 4);
        }

        #pragma unroll
        for (int kk = 0; kk < 16; kk++) {
            float4 a0 = *reinterpret_cast<const float4*>(&As[cur][kk][ty * 4]);
            float4 a1 = *reinterpret_cast<const float4*>(&As[cur][kk][ty * 4 + 128]);
            float4 b0 = *reinterpret_cast<const float4*>(&Bs[cur][kk][tx * 4]);
            float4 b1 = *reinterpret_cast<const float4*>(&Bs[cur][kk][tx * 4 + 32]);
            float av[8] = {a0.x, a0.y, a0.z, a0.w, a1.x, a1.y, a1.z, a1.w};
            float bv[8] = {b0.x, b0.y, b0.z, b0.w, b1.x, b1.y, b1.z, b1.w};
            #pragma unroll
            for (int i = 0; i < 8; i++)
                #pragma unroll
                for (int j = 0; j < 8; j++)
                    acc[i][j] += av[i] * bv[j];
        }

        if (kt < 15) {  // regs -> other smem buffer; single barrier per tile
            const int nxt = cur ^ 1;
            #pragma unroll
            for (int c = 0; c < 4; c++) {
                As[nxt][c * 4 + 0][tid] = aReg[c].x;
                As[nxt][c * 4 + 1][tid] = aReg[c].y;
                As[nxt][c * 4 + 2][tid] = aReg[c].z;
                As[nxt][c * 4 + 3][tid] = aReg[c].w;
            }
            *reinterpret_cast<float4*>(&Bs[nxt][tid >> 4][(tid & 15) * 4]) = bReg;
            __syncthreads();
        }
    }

    #pragma unroll
    for (int i = 0; i < 8; i++) {
        const int row = (i < 4) ? (ty * 4 + i) : (128 + ty * 4 + (i - 4));
        const float b = bias[row];
        if (STATS) {
            float s1 = 0.f, s2 = 0.f;
            #pragma unroll
            for (int j = 0; j < 8; j++) {
                float v = acc[i][j] + b;
                s1 += v; s2 += v * v;
            }
            #pragma unroll
            for (int o = 4; o > 0; o >>= 1) {
                s1 += __shfl_xor_sync(0xffffffffu, s1, o);
                s2 += __shfl_xor_sync(0xffffffffu, s2, o);
            }
            if (tx == 0) {
                atomicAdd(&asum[batch * CCH + row], s1);
                atomicAdd(&asq[batch * CCH + row], s2);
            }
        } else {
            float* Crow = Cout + ((long)batch * CCH + row) * HW + n0;
            float4 o0 = make_float4(acc[i][0] + b, acc[i][1] + b, acc[i][2] + b, acc[i][3] + b);
            float4 o1 = make_float4(acc[i][4] + b, acc[i][5] + b, acc[i][6] + b, acc[i][7] + b);
            *reinterpret_cast<float4*>(Crow + tx * 4)      = o0;
            *reinterpret_cast<float4*>(Crow + tx * 4 + 32) = o1;
        }
    }
}

// -------------------- per-row (n,c) mean / rstd of x ------------------------
__global__ void stats_rows(const float* __restrict__ X)
{
    const int row = blockIdx.x;
    const float4* X4 = reinterpret_cast<const float4*>(X + (long)row * HW);
    float s = 0.f, s2 = 0.f;
    for (int i = threadIdx.x; i < HW / 4; i += 256) {
        float4 v = X4[i];
        s  += v.x + v.y + v.z + v.w;
        s2 += v.x * v.x + v.y * v.y + v.z * v.z + v.w * v.w;
    }
    __shared__ float sm1[8], sm2[8];
    #pragma unroll
    for (int o = 16; o; o >>= 1) {
        s  += __shfl_xor_sync(0xffffffffu, s, o);
        s2 += __shfl_xor_sync(0xffffffffu, s2, o);
    }
    if ((threadIdx.x & 31) == 0) { sm1[threadIdx.x >> 5] = s; sm2[threadIdx.x >> 5] = s2; }
    __syncthreads();
    if (threadIdx.x == 0) {
        float t1 = 0.f, t2 = 0.f;
        #pragma unroll
        for (int w = 0; w < 8; w++) { t1 += sm1[w]; t2 += sm2[w]; }
        float m = t1 / (float)HW;
        float var = t2 / (float)HW - m * m;
        if (var < 0.f) var = 0.f;
        g_mx[row]  = m;
        g_rsx[row] = rsqrtf(var + EPS);
    }
}

// -------------------- softmax over spatial dim for K rows -------------------
__global__ void softmax_rows(float* __restrict__ Kp)
{
    const int row = blockIdx.x;
    float4* R = reinterpret_cast<float4*>(Kp + (long)row * HW);
    const int tid = threadIdx.x;
    __shared__ float sm[8];
    __shared__ float bcast;

    // pass 1: max
    float m = -1e30f;
    for (int i = tid; i < HW / 4; i += 256) {
        float4 v = R[i];
        m = fmaxf(m, fmaxf(fmaxf(v.x, v.y), fmaxf(v.z, v.w)));
    }
    #pragma unroll
    for (int o = 16; o; o >>= 1) m = fmaxf(m, __shfl_xor_sync(0xffffffffu, m, o));
    if ((tid & 31) == 0) sm[tid >> 5] = m;
    __syncthreads();
    if (tid == 0) {
        float t = -1e30f;
        #pragma unroll
        for (int w = 0; w < 8; w++) t = fmaxf(t, sm[w]);
        bcast = t;
    }
    __syncthreads();
    m = bcast;
    __syncthreads();

    // pass 2: sum of exp (row stays L2/L1-resident)
    float s = 0.f;
    for (int i = tid; i < HW / 4; i += 256) {
        float4 v = R[i];
        s += __expf(v.x - m) + __expf(v.y - m) + __expf(v.z - m) + __expf(v.w - m);
    }
    #pragma unroll
    for (int o = 16; o; o >>= 1) s += __shfl_xor_sync(0xffffffffu, s, o);
    if ((tid & 31) == 0) sm[tid >> 5] = s;
    __syncthreads();
    if (tid == 0) {
        float t = 0.f;
        #pragma unroll
        for (int w = 0; w < 8; w++) t += sm[w];
        bcast = t;
    }
    __syncthreads();
    const float inv = 1.f / bcast;

    // pass 3: write normalized
    for (int i = tid; i < HW / 4; i += 256) {
        float4 v = R[i];
        v.x = __expf(v.x - m) * inv; v.y = __expf(v.y - m) * inv;
        v.z = __expf(v.z - m) * inv; v.w = __expf(v.w - m) * inv;
        R[i] = v;
    }
}

// ---------------- softmax over the 32 head-channels for Q -------------------
__global__ void softmax_q(float* __restrict__ Qp)
{
    const int s  = blockIdx.x * 256 + threadIdx.x;  // spatial
    const int nh = blockIdx.y;                      // n*8 + h
    const long base = (long)nh * HCH * HW + s;
    float v[HCH];
    float m = -1e30f;
    #pragma unroll
    for (int c = 0; c < HCH; c++) { v[c] = Qp[base + (long)c * HW]; m = fmaxf(m, v[c]); }
    float sum = 0.f;
    #pragma unroll
    for (int c = 0; c < HCH; c++) { v[c] = __expf(v[c] - m); sum += v[c]; }
    const float inv = 1.f / sum;
    #pragma unroll
    for (int c = 0; c < HCH; c++) Qp[base + (long)c * HW] = v[c] * inv;
}

// ---------------------------- zero accumulators -----------------------------
__global__ void zero_buffers()
{
    const int i = blockIdx.x * 256 + threadIdx.x;
    if (i < NB * NHEADS * HCH * HCH) g_ctx[i] = 0.f;
    if (i < NB * CCH) { g_asum[i] = 0.f; g_asq[i] = 0.f; }
}

// ------------- ctx[n,h] (32x32) = softmax(K)[32,HW] @ V[32,HW]^T ------------
__global__ __launch_bounds__(256) void ctx_kernel()
{
    __shared__ float Ks[32][129];
    __shared__ float Vs[32][129];
    const int tid = threadIdx.x;
    const int nh  = blockIdx.y;
    const long sbase = (long)blockIdx.x * (HW / 16);   // 1024 per split
    const int g  = tid >> 6;        // s-subgroup (4)
    const int t  = tid & 63;
    const int tk = t >> 3;          // 8
    const int tv = t & 7;           // 8

    const float* Kb = g_B1 + (long)nh * HCH * HW;
    const float* Vb = g_B2 + (long)nh * HCH * HW;

    float acc[4][4];
    #pragma unroll
    for (int i = 0; i < 4; i++)
        #pragma unroll
        for (int j = 0; j < 4; j++) acc[i][j] = 0.f;

    for (int s0 = 0; s0 < 1024; s0 += 128) {
        #pragma unroll
        for (int p = 0; p < 4; p++) {
            const int idx = tid + p * 256;
            const int r = idx >> 5, c4 = idx & 31;
            float4 kv = *reinterpret_cast<const float4*>(Kb + (long)r * HW + sbase + s0 + c4 * 4);
            float4 vv = *reinterpret_cast<const float4*>(Vb + (long)r * HW + sbase + s0 + c4 * 4);
            Ks[r][c4 * 4 + 0] = kv.x; Ks[r][c4 * 4 + 1] = kv.y;
            Ks[r][c4 * 4 + 2] = kv.z; Ks[r][c4 * 4 + 3] = kv.w;
            Vs[r][c4 * 4 + 0] = vv.x; Vs[r][c4 * 4 + 1] = vv.y;
            Vs[r][c4 * 4 + 2] = vv.z; Vs[r][c4 * 4 + 3] = vv.w;
        }
        __syncthreads();
        #pragma unroll
        for (int si = 0; si < 32; si++) {
            const int s = g * 32 + si;
            float ka[4], vb[4];
            #pragma unroll
            for (int i = 0; i < 4; i++) ka[i] = Ks[tk * 4 + i][s];
            #pragma unroll
            for (int j = 0; j < 4; j++) vb[j] = Vs[tv * 4 + j][s];
            #pragma unroll
            for (int i = 0; i < 4; i++)
                #pragma unroll
                for (int j = 0; j < 4; j++) acc[i][j] += ka[i] * vb[j];
        }
        __syncthreads();
    }
    float* cb = g_ctx + (long)nh * HCH * HCH;
    #pragma unroll
    for (int i = 0; i < 4; i++)
        #pragma unroll
        for (int j = 0; j < 4; j++)
            atomicAdd(&cb[(tk * 4 + i) * HCH + tv * 4 + j], acc[i][j]);
}

// ------- M[n,c,h*32+k] = sum_v Wr[c, h*32+v] * ctx[n,h,k,v]  (tiny) ---------
__global__ void m_kernel(const float* __restrict__ Wr)
{
    const int nh = blockIdx.x;
    const int n = nh >> 3, h = nh & 7;
    __shared__ float cs[32][33];
    const int tid = threadIdx.x;
    #pragma unroll
    for (int p = 0; p < 4; p++) {
        const int idx = tid + p * 256;
        cs[idx >> 5][idx & 31] = g_ctx[(long)nh * 1024 + idx];
    }
    __syncthreads();
    float wr[HCH];
    #pragma unroll
    for (int v = 0; v < HCH; v++) wr[v] = Wr[tid * CCH + h * HCH + v];
    #pragma unroll
    for (int k = 0; k < HCH; k++) {
        float s = 0.f;
        #pragma unroll
        for (int v = 0; v < HCH; v++) s += wr[v] * cs[k][v];
        g_M[((long)n * CCH + tid) * CCH + h * HCH + k] = s;
    }
}

// ---------------- attn stats -> (ma, sa) ------------------------------------
__global__ void finalize_stats()
{
    const int i = blockIdx.x * 256 + threadIdx.x;   // 2048 total
    const float ma = g_asum[i] / (float)HW;
    float var = g_asq[i] / (float)HW - ma * ma;
    if (var < 0.f) var = 0.f;
    g_ma[i] = ma;
    g_sa[i] = sqrtf(var + EPS);
}

// ---------------- AdaIN: out = sa*(x-mx)*rsx + ma ---------------------------
__global__ void adain(const float* __restrict__ X, float* __restrict__ Out)
{
    const int gi  = blockIdx.x * 256 + threadIdx.x;   // float4 index
    const int row = gi >> 12;                         // HW/4 = 4096 per row
    float4 x = reinterpret_cast<const float4*>(X)[gi];
    const float mx = g_mx[row], rs = g_rsx[row];
    const float ma = g_ma[row], sa = g_sa[row];
    float4 o;
    o.x = sa * (x.x - mx) * rs + ma;
    o.y = sa * (x.y - mx) * rs + ma;
    o.z = sa * (x.z - mx) * rs + ma;
    o.w = sa * (x.w - mx) * rs + ma;
    reinterpret_cast<float4*>(Out)[gi] = o;
}

// ---------------------------------------------------------------------------
extern "C" void kernel_launch(void* const* d_in, const int* in_sizes, int n_in,
                              void* d_out, int out_size)
{
    const float* x  = (const float*)d_in[0];
    const float* y  = (const float*)d_in[1];
    const float* Wq = (const float*)d_in[2];
    const float* bq = (const float*)d_in[3];
    const float* Wk = (const float*)d_in[4];
    const float* bk = (const float*)d_in[5];
    const float* Wv = (const float*)d_in[6];
    const float* bv = (const float*)d_in[7];
    const float* Wr = (const float*)d_in[8];
    const float* br = (const float*)d_in[9];
    float* out = (float*)d_out;

    float *pB1, *pB2, *pM, *pasum, *pasq;
    cudaGetSymbolAddress((void**)&pB1,   g_B1);
    cudaGetSymbolAddress((void**)&pB2,   g_B2);
    cudaGetSymbolAddress((void**)&pM,    g_M);
    cudaGetSymbolAddress((void**)&pasum, g_asum);
    cudaGetSymbolAddress((void**)&pasq,  g_asq);

    const dim3 gemmGrid(HW / 64, 1, NB);

    stats_rows<<<NB * CCH, 256>>>(x);
    zero_buffers<<<256, 256>>>();

    // K and V first (into B1 / B2), consume them, then reuse B1 for Q.
    gemm_k256<false><<<gemmGrid, 256>>>(Wk, 0, y, bk, pB1, nullptr, nullptr);
    gemm_k256<false><<<gemmGrid, 256>>>(Wv, 0, y, bv, pB2, nullptr, nullptr);

    softmax_rows<<<NB * CCH, 256>>>(pB1);           // K softmax over spatial
    ctx_kernel<<<dim3(16, NB * NHEADS), 256>>>();   // K,V -> ctx
    m_kernel<<<NB * NHEADS, 256>>>(Wr);             // fold Wr into ctx -> M

    gemm_k256<false><<<gemmGrid, 256>>>(Wq, 0, x, bq, pB1, nullptr, nullptr);  // Q into B1
    softmax_q<<<dim3(HW / 256, NB * NHEADS), 256>>>(pB1);

    // attn = M @ Qsm, consumed only as per-row stats
    gemm_k256<true><<<gemmGrid, 256>>>(pM, (long)CCH * CCH, pB1, br,
                                       nullptr, pasum, pasq);

    finalize_stats<<<NB * CCH / 256, 256>>>();
    adain<<<NB * CCH * HW / 4 / 256, 256>>>(x, out);
}

// round 6
// speedup vs baseline: 2.2802x; 2.2802x over previous
#include <cuda_runtime.h>
#include <cstdint>
#include <math.h>

#define NB     8
#define CCH    256
#define HW     16384
#define NHEADS 8
#define HCH    32
#define EPS    1e-5f

// ---------------- scratch (static device arrays; no cudaMalloc) -------------
__device__ float g_K[NB * CCH * HW];    // 128 MB
__device__ float g_V[NB * CCH * HW];    // 128 MB
__device__ float g_Q[NB * CCH * HW];    // 128 MB (softmaxed Q)
__device__ float g_ctx[NB * NHEADS * HCH * HCH];
__device__ float g_M[NB * CCH * CCH];
__device__ float g_mx[NB * CCH];
__device__ float g_rsx[NB * CCH];
__device__ float g_asum[NB * CCH];
__device__ float g_asq[NB * CCH];
__device__ float g_ma[NB * CCH];
__device__ float g_sa[NB * CCH];

// tf32 mma: D(16x8) += A(16x8) * B(8x8). Portable (sm_80+), legal on sm_100.
#define MMA_TF32(d, a0, a1, a2, a3, b0, b1)                                    \
    asm volatile("mma.sync.aligned.m16n8k8.row.col.f32.tf32.tf32.f32 "         \
                 "{%0,%1,%2,%3}, {%4,%5,%6,%7}, {%8,%9}, {%0,%1,%2,%3};"       \
                 : "+f"((d)[0]), "+f"((d)[1]), "+f"((d)[2]), "+f"((d)[3])      \
                 : "r"(a0), "r"(a1), "r"(a2), "r"(a3), "r"(b0), "r"(b1))

// ======================= TF32 tensor-core GEMM ==============================
// C[b](256 x HW) = A[b](256x256) @ B[b](256 x HW) + bias
// grid (HW/128, 2 m-halves, NB); 256 threads = 8 warps (2Mx4N), warp = 64x32.
// Block K-tile 16, double buffered, regs-prefetch, ONE __syncthreads per tile.
// MODE 0: +bias, store (K/V).  MODE 1: +bias, per-head (32-row) softmax in
// registers via xor-4/8/16 shfl groups, store (Q).  MODE 2: +bias, row
// sum/sumsq atomics only, no store (attn consumed only as AdaIN stats).
template <int MODE>
__global__ __launch_bounds__(256, 2)
void gemm_tf32(const float* __restrict__ A, long aStride,
               const float* __restrict__ B,
               const float* __restrict__ bias,
               float* __restrict__ Cout,
               float* __restrict__ asum, float* __restrict__ asq)
{
    __shared__ float As[2][128][20];   // [m][k] 16 used + pad (conflict-free frags)
    __shared__ float Bs[2][16][136];   // [k][n] 128 used + pad

    const int tid = threadIdx.x, lane = tid & 31, wid = tid >> 5;
    const int batch = blockIdx.z, mhalf = blockIdx.y, n0 = blockIdx.x * 128;
    const int g = lane >> 2, tg = lane & 3;
    const int Moff = (wid >> 2) * 64, Noff = (wid & 3) * 32;

    const float* Ab = A + (long)batch * aStride + (long)(mhalf * 128) * CCH;
    const float* Bb = B + (long)batch * CCH * HW;

    // per-thread gmem slots: A 2 x float4 (rows tid>>2 (+64), cols (tid&3)*4),
    // B 2 x float4 (rows tid>>5 (+8), cols (tid&31)*4)
    const int ar = tid >> 2, ac = (tid & 3) * 4;
    const int brr = tid >> 5, bcc = (tid & 31) * 4;

    float4 aR[2], bR[2];
    auto fetch = [&](int kt) {
        aR[0] = *reinterpret_cast<const float4*>(Ab + (long)ar * CCH + kt * 16 + ac);
        aR[1] = *reinterpret_cast<const float4*>(Ab + (long)(ar + 64) * CCH + kt * 16 + ac);
        bR[0] = *reinterpret_cast<const float4*>(Bb + (long)(kt * 16 + brr) * HW + n0 + bcc);
        bR[1] = *reinterpret_cast<const float4*>(Bb + (long)(kt * 16 + brr + 8) * HW + n0 + bcc);
    };
    auto stash = [&](int bf) {
        *reinterpret_cast<float4*>(&As[bf][ar     ][ac]) = aR[0];
        *reinterpret_cast<float4*>(&As[bf][ar + 64][ac]) = aR[1];
        *reinterpret_cast<float4*>(&Bs[bf][brr    ][bcc]) = bR[0];
        *reinterpret_cast<float4*>(&Bs[bf][brr + 8][bcc]) = bR[1];
    };

    float acc[4][4][4];
    #pragma unroll
    for (int i = 0; i < 4; i++)
        #pragma unroll
        for (int j = 0; j < 4; j++)
            #pragma unroll
            for (int c = 0; c < 4; c++) acc[i][j][c] = 0.f;

    fetch(0);
    stash(0);
    __syncthreads();

    #pragma unroll 1
    for (int kt = 0; kt < 16; kt++) {
        const int bf = kt & 1;
        if (kt < 15) fetch(kt + 1);           // gmem -> regs, overlapped w/ MMAs

        #pragma unroll
        for (int ks = 0; ks < 2; ks++) {      // two k8 steps per tile
            uint32_t a[4][4], b[4][2];
            #pragma unroll
            for (int mf = 0; mf < 4; mf++) {
                const int r = Moff + mf * 16 + g, k = ks * 8 + tg;
                a[mf][0] = __float_as_uint(As[bf][r    ][k    ]);
                a[mf][1] = __float_as_uint(As[bf][r + 8][k    ]);
                a[mf][2] = __float_as_uint(As[bf][r    ][k + 4]);
                a[mf][3] = __float_as_uint(As[bf][r + 8][k + 4]);
            }
            #pragma unroll
            for (int nf = 0; nf < 4; nf++) {
                const int cn = Noff + nf * 8 + g, k = ks * 8 + tg;
                b[nf][0] = __float_as_uint(Bs[bf][k    ][cn]);
                b[nf][1] = __float_as_uint(Bs[bf][k + 4][cn]);
            }
            #pragma unroll
            for (int mf = 0; mf < 4; mf++)
                #pragma unroll
                for (int nf = 0; nf < 4; nf++)
                    MMA_TF32(acc[mf][nf], a[mf][0], a[mf][1], a[mf][2], a[mf][3],
                             b[nf][0], b[nf][1]);
        }

        if (kt < 15) {                        // regs -> other buffer; 1 sync/tile
            stash(bf ^ 1);
            __syncthreads();
        }
    }

    // ----------------------------- epilogue ---------------------------------
    int rowg[4];
    #pragma unroll
    for (int mf = 0; mf < 4; mf++) {
        rowg[mf] = mhalf * 128 + Moff + mf * 16 + g;
        const float b0 = bias[rowg[mf]], b1 = bias[rowg[mf] + 8];
        #pragma unroll
        for (int nf = 0; nf < 4; nf++) {
            acc[mf][nf][0] += b0; acc[mf][nf][1] += b0;
            acc[mf][nf][2] += b1; acc[mf][nf][3] += b1;
        }
    }

    if (MODE == 1) {
        // per-head softmax: head = 32 rows = mf pair {2hl,2hl+1}; one column's
        // 32 row-values = 4 regs x the 8-lane xor-{4,8,16} (g) shfl group.
        #pragma unroll
        for (int hl = 0; hl < 2; hl++)
            #pragma unroll
            for (int nf = 0; nf < 4; nf++)
                #pragma unroll
                for (int ci = 0; ci < 2; ci++) {
                    float v0 = acc[2*hl  ][nf][ci], v1 = acc[2*hl  ][nf][ci + 2];
                    float v2 = acc[2*hl+1][nf][ci], v3 = acc[2*hl+1][nf][ci + 2];
                    float m = fmaxf(fmaxf(v0, v1), fmaxf(v2, v3));
                    #pragma unroll
                    for (int o = 4; o <= 16; o <<= 1)
                        m = fmaxf(m, __shfl_xor_sync(0xffffffffu, m, o));
                    v0 = __expf(v0 - m); v1 = __expf(v1 - m);
                    v2 = __expf(v2 - m); v3 = __expf(v3 - m);
                    float s = v0 + v1 + v2 + v3;
                    #pragma unroll
                    for (int o = 4; o <= 16; o <<= 1)
                        s += __shfl_xor_sync(0xffffffffu, s, o);
                    const float inv = 1.f / s;
                    acc[2*hl  ][nf][ci] = v0 * inv; acc[2*hl  ][nf][ci + 2] = v1 * inv;
                    acc[2*hl+1][nf][ci] = v2 * inv; acc[2*hl+1][nf][ci + 2] = v3 * inv;
                }
    }

    if (MODE == 2) {
        #pragma unroll
        for (int mf = 0; mf < 4; mf++) {
            float s0 = 0.f, q0 = 0.f, s1 = 0.f, q1 = 0.f;
            #pragma unroll
            for (int nf = 0; nf < 4; nf++) {
                s0 += acc[mf][nf][0] + acc[mf][nf][1];
                q0 += acc[mf][nf][0]*acc[mf][nf][0] + acc[mf][nf][1]*acc[mf][nf][1];
                s1 += acc[mf][nf][2] + acc[mf][nf][3];
                q1 += acc[mf][nf][2]*acc[mf][nf][2] + acc[mf][nf][3]*acc[mf][nf][3];
            }
            #pragma unroll
            for (int o = 1; o <= 2; o <<= 1) {   // reduce 4-lane tg group
                s0 += __shfl_xor_sync(0xffffffffu, s0, o);
                q0 += __shfl_xor_sync(0xffffffffu, q0, o);
                s1 += __shfl_xor_sync(0xffffffffu, s1, o);
                q1 += __shfl_xor_sync(0xffffffffu, q1, o);
            }
            if (tg == 0) {
                atomicAdd(&asum[batch * CCH + rowg[mf]    ], s0);
                atomicAdd(&asq [batch * CCH + rowg[mf]    ], q0);
                atomicAdd(&asum[batch * CCH + rowg[mf] + 8], s1);
                atomicAdd(&asq [batch * CCH + rowg[mf] + 8], q1);
            }
        }
    } else {
        #pragma unroll
        for (int mf = 0; mf < 4; mf++)
            #pragma unroll
            for (int nf = 0; nf < 4; nf++) {
                const int col = n0 + Noff + nf * 8 + tg * 2;
                float* p0 = Cout + ((long)batch * CCH + rowg[mf]) * HW + col;
                *reinterpret_cast<float2*>(p0) = make_float2(acc[mf][nf][0], acc[mf][nf][1]);
                *reinterpret_cast<float2*>(p0 + 8L * HW) = make_float2(acc[mf][nf][2], acc[mf][nf][3]);
            }
    }
}

// -------------------- per-row (n,c) mean / rstd of x ------------------------
__global__ void stats_rows(const float* __restrict__ X)
{
    const int row = blockIdx.x;
    const float4* X4 = reinterpret_cast<const float4*>(X + (long)row * HW);
    float s = 0.f, s2 = 0.f;
    for (int i = threadIdx.x; i < HW / 4; i += 256) {
        float4 v = X4[i];
        s += v.x + v.y + v.z + v.w;
        s2 += v.x*v.x + v.y*v.y + v.z*v.z + v.w*v.w;
    }
    __shared__ float sm1[8], sm2[8];
    #pragma unroll
    for (int o = 16; o; o >>= 1) {
        s  += __shfl_xor_sync(0xffffffffu, s, o);
        s2 += __shfl_xor_sync(0xffffffffu, s2, o);
    }
    if ((threadIdx.x & 31) == 0) { sm1[threadIdx.x >> 5] = s; sm2[threadIdx.x >> 5] = s2; }
    __syncthreads();
    if (threadIdx.x == 0) {
        float t1 = 0.f, t2 = 0.f;
        #pragma unroll
        for (int w = 0; w < 8; w++) { t1 += sm1[w]; t2 += sm2[w]; }
        const float m = t1 / (float)HW;
        float var = t2 / (float)HW - m * m;
        if (var < 0.f) var = 0.f;
        g_mx[row] = m;
        g_rsx[row] = rsqrtf(var + EPS);
    }
}

// -------------------- softmax over spatial dim for K rows -------------------
__global__ void softmax_rows(float* __restrict__ Kp)
{
    const int row = blockIdx.x, tid = threadIdx.x;
    float4* R = reinterpret_cast<float4*>(Kp + (long)row * HW);
    __shared__ float sm[8];
    __shared__ float bc;

    float m = -1e30f;
    for (int i = tid; i < HW / 4; i += 256) {
        float4 v = R[i];
        m = fmaxf(m, fmaxf(fmaxf(v.x, v.y), fmaxf(v.z, v.w)));
    }
    #pragma unroll
    for (int o = 16; o; o >>= 1) m = fmaxf(m, __shfl_xor_sync(0xffffffffu, m, o));
    if ((tid & 31) == 0) sm[tid >> 5] = m;
    __syncthreads();
    if (tid == 0) {
        float t = -1e30f;
        #pragma unroll
        for (int w = 0; w < 8; w++) t = fmaxf(t, sm[w]);
        bc = t;
    }
    __syncthreads();
    m = bc; __syncthreads();

    float s = 0.f;
    for (int i = tid; i < HW / 4; i += 256) {
        float4 v = R[i];
        s += __expf(v.x - m) + __expf(v.y - m) + __expf(v.z - m) + __expf(v.w - m);
    }
    #pragma unroll
    for (int o = 16; o; o >>= 1) s += __shfl_xor_sync(0xffffffffu, s, o);
    if ((tid & 31) == 0) sm[tid >> 5] = s;
    __syncthreads();
    if (tid == 0) {
        float t = 0.f;
        #pragma unroll
        for (int w = 0; w < 8; w++) t += sm[w];
        bc = t;
    }
    __syncthreads();
    const float inv = 1.f / bc;
    for (int i = tid; i < HW / 4; i += 256) {
        float4 v = R[i];
        v.x = __expf(v.x - m) * inv; v.y = __expf(v.y - m) * inv;
        v.z = __expf(v.z - m) * inv; v.w = __expf(v.w - m) * inv;
        R[i] = v;
    }
}

__global__ void zero_buffers()
{
    const int i = blockIdx.x * 256 + threadIdx.x;
    if (i < NB * NHEADS * HCH * HCH) g_ctx[i] = 0.f;
    if (i < NB * CCH) { g_asum[i] = 0.f; g_asq[i] = 0.f; }
}

// ------------- ctx[n,h] (32x32) = softmaxK[32,HW] @ V[32,HW]^T --------------
__global__ __launch_bounds__(256) void ctx_kernel()
{
    __shared__ float Ks[32][129];
    __shared__ float Vs[32][129];
    const int tid = threadIdx.x, nh = blockIdx.y;
    const long sbase = (long)blockIdx.x * (HW / 16);
    const int gq = tid >> 6, t = tid & 63, tk = t >> 3, tv = t & 7;
    const float* Kb = g_K + (long)nh * HCH * HW;
    const float* Vb = g_V + (long)nh * HCH * HW;

    float acc[4][4];
    #pragma unroll
    for (int i = 0; i < 4; i++)
        #pragma unroll
        for (int j = 0; j < 4; j++) acc[i][j] = 0.f;

    for (int s0 = 0; s0 < 1024; s0 += 128) {
        #pragma unroll
        for (int p = 0; p < 4; p++) {
            const int idx = tid + p * 256;
            const int r = idx >> 5, c4 = idx & 31;
            float4 kv = *reinterpret_cast<const float4*>(Kb + (long)r * HW + sbase + s0 + c4 * 4);
            float4 vv = *reinterpret_cast<const float4*>(Vb + (long)r * HW + sbase + s0 + c4 * 4);
            Ks[r][c4*4+0] = kv.x; Ks[r][c4*4+1] = kv.y; Ks[r][c4*4+2] = kv.z; Ks[r][c4*4+3] = kv.w;
            Vs[r][c4*4+0] = vv.x; Vs[r][c4*4+1] = vv.y; Vs[r][c4*4+2] = vv.z; Vs[r][c4*4+3] = vv.w;
        }
        __syncthreads();
        #pragma unroll
        for (int si = 0; si < 32; si++) {
            const int s = gq * 32 + si;
            float ka[4], vb[4];
            #pragma unroll
            for (int i = 0; i < 4; i++) ka[i] = Ks[tk * 4 + i][s];
            #pragma unroll
            for (int j = 0; j < 4; j++) vb[j] = Vs[tv * 4 + j][s];
            #pragma unroll
            for (int i = 0; i < 4; i++)
                #pragma unroll
                for (int j = 0; j < 4; j++) acc[i][j] += ka[i] * vb[j];
        }
        __syncthreads();
    }
    float* cb = g_ctx + (long)nh * HCH * HCH;
    #pragma unroll
    for (int i = 0; i < 4; i++)
        #pragma unroll
        for (int j = 0; j < 4; j++)
            atomicAdd(&cb[(tk * 4 + i) * HCH + tv * 4 + j], acc[i][j]);
}

// ------- M[n,c,h*32+k] = sum_v Wr[c,h*32+v] * ctx[n,h,k,v] ------------------
__global__ void m_kernel(const float* __restrict__ Wr)
{
    const int nh = blockIdx.x, n = nh >> 3, h = nh & 7, tid = threadIdx.x;
    __shared__ float cs[32][33];
    #pragma unroll
    for (int p = 0; p < 4; p++) {
        const int idx = tid + p * 256;
        cs[idx >> 5][idx & 31] = g_ctx[(long)nh * 1024 + idx];
    }
    __syncthreads();
    float wr[HCH];
    #pragma unroll
    for (int v = 0; v < HCH; v++) wr[v] = Wr[tid * CCH + h * HCH + v];
    #pragma unroll
    for (int k = 0; k < HCH; k++) {
        float s = 0.f;
        #pragma unroll
        for (int v = 0; v < HCH; v++) s += wr[v] * cs[k][v];
        g_M[((long)n * CCH + tid) * CCH + h * HCH + k] = s;
    }
}

__global__ void finalize_stats()
{
    const int i = blockIdx.x * 256 + threadIdx.x;
    const float ma = g_asum[i] / (float)HW;
    float var = g_asq[i] / (float)HW - ma * ma;
    if (var < 0.f) var = 0.f;
    g_ma[i] = ma;
    g_sa[i] = sqrtf(var + EPS);
}

__global__ void adain(const float* __restrict__ X, float* __restrict__ Out)
{
    const int gi = blockIdx.x * 256 + threadIdx.x;
    const int row = gi >> 12;
    float4 x = reinterpret_cast<const float4*>(X)[gi];
    const float mx = g_mx[row], rs = g_rsx[row], ma = g_ma[row], sa = g_sa[row];
    float4 o;
    o.x = sa * (x.x - mx) * rs + ma; o.y = sa * (x.y - mx) * rs + ma;
    o.z = sa * (x.z - mx) * rs + ma; o.w = sa * (x.w - mx) * rs + ma;
    reinterpret_cast<float4*>(Out)[gi] = o;
}

// ---------------------------------------------------------------------------
extern "C" void kernel_launch(void* const* d_in, const int* in_sizes, int n_in,
                              void* d_out, int out_size)
{
    const float* x  = (const float*)d_in[0];
    const float* y  = (const float*)d_in[1];
    const float* Wq = (const float*)d_in[2];
    const float* bq = (const float*)d_in[3];
    const float* Wk = (const float*)d_in[4];
    const float* bk = (const float*)d_in[5];
    const float* Wv = (const float*)d_in[6];
    const float* bv = (const float*)d_in[7];
    const float* Wr = (const float*)d_in[8];
    const float* br = (const float*)d_in[9];
    float* out = (float*)d_out;

    float *pK, *pV, *pQ, *pM, *pas, *pas2;
    cudaGetSymbolAddress((void**)&pK, g_K);
    cudaGetSymbolAddress((void**)&pV, g_V);
    cudaGetSymbolAddress((void**)&pQ, g_Q);
    cudaGetSymbolAddress((void**)&pM, g_M);
    cudaGetSymbolAddress((void**)&pas, g_asum);
    cudaGetSymbolAddress((void**)&pas2, g_asq);

    const dim3 gg(HW / 128, 2, NB);

    stats_rows<<<NB * CCH, 256>>>(x);
    zero_buffers<<<256, 256>>>();

    gemm_tf32<0><<<gg, 256>>>(Wk, 0, y, bk, pK, nullptr, nullptr);
    gemm_tf32<0><<<gg, 256>>>(Wv, 0, y, bv, pV, nullptr, nullptr);

    softmax_rows<<<NB * CCH, 256>>>(pK);
    ctx_kernel<<<dim3(16, NB * NHEADS), 256>>>();
    m_kernel<<<NB * NHEADS, 256>>>(Wr);

    gemm_tf32<1><<<gg, 256>>>(Wq, 0, x, bq, pQ, nullptr, nullptr);   // Q + fused head softmax

    gemm_tf32<2><<<gg, 256>>>(pM, (long)CCH * CCH, pQ, br, nullptr, pas, pas2);

    finalize_stats<<<NB * CCH / 256, 256>>>();
    adain<<<NB * CCH * HW / 4 / 256, 256>>>(x, out);
}